// round 16
// baseline (speedup 1.0000x reference)
#include <cuda_runtime.h>
#include <math_constants.h>

#define TILE 256
#define NTHREADS 256
#define NWARPS (NTHREADS / 32)

__global__ __launch_bounds__(NTHREADS)
void gabor_render_kernel(const float* __restrict__ amp,
                         const float* __restrict__ tau,
                         const float* __restrict__ omega,
                         const float* __restrict__ sigma,
                         const float* __restrict__ phi,
                         const float* __restrict__ gamma,
                         float* __restrict__ out,
                         int T, int N)
{
    // Compacted per-atom params for this tile:
    // p1 = {amp, tau, 4*sigma, 1/(2*sigma^2 + 1e-8)}
    // p2 = {omega, 0.5*gamma, phi, 0}
    __shared__ float4 s_p1[TILE];
    __shared__ float4 s_p2[TILE];
    __shared__ int s_wcnt[NWARPS];

    const int tile0 = blockIdx.x * TILE;
    const int i = tile0 + threadIdx.x;

    // HYPOTHESIS (last untested cell of the matrix): reference t is the
    // MATERIALIZED product  t = round_f32(i * f32(1/24000))  (XLA algsimp
    // rewrites /const into *recip, and t is a separate array, so the
    // product IS rounded before the subtraction fusion).
    // __fmul_rn is contraction-proof — unlike R9/R11 where NVVM silently
    // fused the single-use mul into an fma and tested the wrong thing.
    const float INV_SR = 1.0f / 24000.0f;              // f32 0x3832D2DA
    const float t = __fmul_rn((float)i, INV_SR);

    // Conservative tile bounds (padded; per-sample mask is exact).
    const float t_lo = (float)tile0 * INV_SR - 1e-5f;
    const float t_hi = (float)(tile0 + TILE - 1) * INV_SR + 1e-5f;

    const int lane = threadIdx.x & 31;
    const int warp = threadIdx.x >> 5;

    float acc = 0.0f;
    const float TWO_PI_F = 6.28318530717958647692f;    // f32 0x40C90FDB

    for (int base = 0; base < N; base += TILE) {
        const int aidx = base + threadIdx.x;

        // ---- tile-level atom window test ----
        bool pred = false;
        float a_tu = 0.f, a_sg = 0.f;
        if (aidx < N) {
            a_tu = tau[aidx];
            a_sg = sigma[aidx];
            float r = 4.0f * a_sg;
            pred = (a_tu - r <= t_hi) && (a_tu + r >= t_lo);
        }

        // ---- deterministic ordered compaction (ballot + popc prefix) ----
        unsigned bal = __ballot_sync(0xffffffffu, pred);
        if (lane == 0) s_wcnt[warp] = __popc(bal);
        __syncthreads();
        int warp_base = 0;
        int cnt = 0;
        #pragma unroll
        for (int w = 0; w < NWARPS; w++) {
            int c = s_wcnt[w];
            if (w < warp) warp_base += c;
            cnt += c;
        }
        __syncthreads();

        if (pred) {
            int pos = warp_base + __popc(bal & ((1u << lane) - 1u));
            float sg = a_sg;
            float r = 4.0f * sg;                               // exact
            float F = __fadd_rn(2.0f * __fmul_rn(sg, sg), 1e-8f);
            float rcpF = __frcp_rn(F);   // env path not error-amplified
            s_p1[pos] = make_float4(amp[aidx], a_tu, r, rcpF);
            s_p2[pos] = make_float4(omega[aidx], 0.5f * gamma[aidx],
                                    phi[aidx], 0.0f);
        }
        __syncthreads();

        // ---- dense compute over compacted atoms ----
        for (int k = 0; k < cnt; k++) {
            float4 p1 = s_p1[k];
            float4 p2 = s_p2[k];

            // tc = (rounded t) - tau, contraction-proof.
            float tc = __fadd_rn(t, -p1.y);

            // phase: strict f32 rounding, non-contracted:
            //   f32(2pi) * (om*tc + (0.5*gm*tc)*tc) + phi
            float A  = __fmul_rn(p2.x, tc);
            float B  = __fmul_rn(__fmul_rn(p2.y, tc), tc);
            float S  = __fadd_rn(A, B);
            float ph = __fadd_rn(__fmul_rn(TWO_PI_F, S), p2.z);
            float c  = __cosf(ph);   // measured ⊥-equivalent to accurate cos

            float t2 = __fmul_rn(tc, tc);
            float e  = __expf(-(t2 * p1.w));

            float v  = __fmul_rn(__fmul_rn(p1.x, e), c);
            acc += (fabsf(tc) <= p1.z) ? v : 0.0f;
        }
        __syncthreads();  // protect s_p1/s_p2 before next chunk overwrites
    }

    if (i < T) out[i] = acc;
}

extern "C" void kernel_launch(void* const* d_in, const int* in_sizes, int n_in,
                              void* d_out, int out_size)
{
    const float* amp   = (const float*)d_in[0];
    const float* tau   = (const float*)d_in[1];
    const float* omega = (const float*)d_in[2];
    const float* sigma = (const float*)d_in[3];
    const float* phi   = (const float*)d_in[4];
    const float* gamma = (const float*)d_in[5];
    // d_in[6] = num_samples (device scalar) — T available as out_size.

    float* out = (float*)d_out;
    const int T = out_size;
    const int N = in_sizes[0];

    const int grid = (T + TILE - 1) / TILE;
    gabor_render_kernel<<<grid, NTHREADS>>>(amp, tau, omega, sigma, phi, gamma,
                                            out, T, N);
}

// round 17
// speedup vs baseline: 1.0013x; 1.0013x over previous
#include <cuda_runtime.h>
#include <math_constants.h>

#define TILE 256
#define NTHREADS 256
#define NWARPS (NTHREADS / 32)

__device__ __forceinline__ float ex2_approx(float x)
{
    float r;
    asm("ex2.approx.ftz.f32 %0, %1;" : "=f"(r) : "f"(x));
    return r;
}

__global__ __launch_bounds__(NTHREADS)
void gabor_render_kernel(const float* __restrict__ amp,
                         const float* __restrict__ tau,
                         const float* __restrict__ omega,
                         const float* __restrict__ sigma,
                         const float* __restrict__ phi,
                         const float* __restrict__ gamma,
                         float* __restrict__ out,
                         int T, int N)
{
    // Compacted per-atom params:
    // p1 = {amp, tau, 4*sigma, -log2(e)/(2*sigma^2+1e-8)}
    // p2 = {2*pi*omega, pi*gamma, phi, 0}
    __shared__ float4 s_p1[TILE + 1];
    __shared__ float4 s_p2[TILE + 1];
    __shared__ int s_wcnt[NWARPS];

    const int tile0 = blockIdx.x * TILE;
    const int i = tile0 + threadIdx.x;

    // LOAD-BEARING (R16): reference t is the materialized rounded product
    // i * f32(1/24000). Intrinsics keep NVVM from contracting it away.
    const float INV_SR = 1.0f / 24000.0f;
    const float t = __fmul_rn((float)i, INV_SR);

    const float t_lo = (float)tile0 * INV_SR - 1e-5f;
    const float t_hi = (float)(tile0 + TILE - 1) * INV_SR + 1e-5f;

    const int lane = threadIdx.x & 31;
    const int warp = threadIdx.x >> 5;

    const float TWO_PI_F = 6.28318530717958647692f;
    const float PI_F     = 3.14159265358979323846f;
    const float NLOG2E_F = -1.44269504088896340736f;

    float acc = 0.0f;

    for (int base = 0; base < N; base += TILE) {
        const int aidx = base + threadIdx.x;

        // ---- tile-level atom window test ----
        bool pred = false;
        float a_tu = 0.f, a_sg = 0.f;
        if (aidx < N) {
            a_tu = tau[aidx];
            a_sg = sigma[aidx];
            float r = 4.0f * a_sg;
            pred = (a_tu - r <= t_hi) && (a_tu + r >= t_lo);
        }

        // ---- deterministic ordered compaction (ballot + popc prefix) ----
        unsigned bal = __ballot_sync(0xffffffffu, pred);
        if (lane == 0) s_wcnt[warp] = __popc(bal);
        __syncthreads();
        int warp_base = 0;
        int cnt = 0;
        #pragma unroll
        for (int w = 0; w < NWARPS; w++) {
            int c = s_wcnt[w];
            if (w < warp) warp_base += c;
            cnt += c;
        }
        __syncthreads();

        if (pred) {
            int pos = warp_base + __popc(bal & ((1u << lane) - 1u));
            float sg = a_sg;
            float r = 4.0f * sg;                               // exact
            float F = __fadd_rn(2.0f * __fmul_rn(sg, sg), 1e-8f);
            float rcpFe = __frcp_rn(F) * NLOG2E_F;   // env: not amplified
            s_p1[pos] = make_float4(amp[aidx], a_tu, r, rcpFe);
            s_p2[pos] = make_float4(TWO_PI_F * omega[aidx],
                                    PI_F * gamma[aidx],
                                    phi[aidx], 0.0f);
        }
        // Dummy atom to make cnt even: radius -1 -> mask always false.
        if (threadIdx.x == 0 && (cnt & 1)) {
            s_p1[cnt] = make_float4(0.0f, 0.0f, -1.0f, 0.0f);
            s_p2[cnt] = make_float4(0.0f, 0.0f, 0.0f, 0.0f);
        }
        __syncthreads();

        const int cnt2 = (cnt + 1) & ~1;

        // ---- dense compute, 2 atoms per iteration (independent chains) ----
        for (int k = 0; k < cnt2; k += 2) {
            float4 p1a = s_p1[k];
            float4 p2a = s_p2[k];
            float4 p1b = s_p1[k + 1];
            float4 p2b = s_p2[k + 1];

            // LOAD-BEARING: tc via add.rn of the rounded t (no contraction).
            float tca = __fadd_rn(t, -p1a.y);
            float tcb = __fadd_rn(t, -p1b.y);

            // phase = (pi*g*tc + 2*pi*om)*tc + phi  (2 fma; ~1e-4 rad rms
            // deviation from ref chain — inside budget, floor was 3.3e-5)
            float pha = fmaf(fmaf(p2a.y, tca, p2a.x), tca, p2a.z);
            float phb = fmaf(fmaf(p2b.y, tcb, p2b.x), tcb, p2b.z);
            float ca = __cosf(pha);
            float cb = __cosf(phb);

            float t2a = tca * tca;
            float t2b = tcb * tcb;
            float ea = ex2_approx(t2a * p1a.w);   // exp(-tc^2/(2s^2+1e-8))
            float eb = ex2_approx(t2b * p1b.w);

            float va = (p1a.x * ea) * ca;
            float vb = (p1b.x * eb) * cb;

            acc += (fabsf(tca) <= p1a.z) ? va : 0.0f;
            acc += (fabsf(tcb) <= p1b.z) ? vb : 0.0f;
        }
        __syncthreads();  // protect s_p1/s_p2 before next chunk overwrites
    }

    if (i < T) out[i] = acc;
}

extern "C" void kernel_launch(void* const* d_in, const int* in_sizes, int n_in,
                              void* d_out, int out_size)
{
    const float* amp   = (const float*)d_in[0];
    const float* tau   = (const float*)d_in[1];
    const float* omega = (const float*)d_in[2];
    const float* sigma = (const float*)d_in[3];
    const float* phi   = (const float*)d_in[4];
    const float* gamma = (const float*)d_in[5];
    // d_in[6] = num_samples (device scalar) — T available as out_size.

    float* out = (float*)d_out;
    const int T = out_size;
    const int N = in_sizes[0];

    const int grid = (T + TILE - 1) / TILE;
    gabor_render_kernel<<<grid, NTHREADS>>>(amp, tau, omega, sigma, phi, gamma,
                                            out, T, N);
}